// round 16
// baseline (speedup 1.0000x reference)
#include <cuda_runtime.h>
#include <cuda_bf16.h>

// Batched LSAP -> mean of matched original entries, one warp per matrix.
// Normalization skipped (monotone affine => same optimal assignment).
//
// Full Jonker-Volgenant pipeline per matrix (lane L owns cols/rows {4L..4L+3}):
//   A)  column reduction (v[j]=min_i C[i,j], argmin rows claimed)
//   A') reduction transfer: for each assigned row i with match j1,
//       mu = min_{j!=j1}(C[i,j]-v[j]); u[i]=mu; v[j1]=C[i,j1]-mu.
//   B)  augmenting row reduction over a FIFO free-row queue (budgeted):
//       process free rows; a steal displaces a row which re-enters the queue.
//       Runs to convergence (or budget), leaving very few rows for SAP.
//   C)  shortest augmenting path over the surviving free list, with BIASED
//       (+4) positive potentials: raw float bits are order-correct, so
//         key = (bits(rm) & 0xFFFFFF00) | (row4col[col]+1)
//       and one __reduce_min_sync yields next row AND popped potential.
//       Frozen columns: w=-1e30 -> rm == exactly 1e30 -> self-excluding keys.

#define NN 128
#define BATCH 128
#define INF_F   1e30f
#define NEG_BIG -1e30f
#define DU_SENT -1e30f
#define BIAS    4.0f
#define FULL 0xffffffffu
#define VMASK 0xFFFFFF00u
#define FROZEN_KEY 0x7149F200u   /* __float_as_uint(1e30f) & VMASK */
#define ARR_BUDGET 768
#define LIST_CAP   (ARR_BUDGET + NN)

__device__ float g_partial[BATCH];
__device__ unsigned g_count = 0;

#define SEL4(s, a0, a1, a2, a3) ((s) < 2 ? ((s) == 0 ? (a0) : (a1)) \
                                         : ((s) == 2 ? (a2) : (a3)))
#define SET4(s, a0, a1, a2, a3, val) do {            \
    if      ((s) == 0) a0 = (val);                   \
    else if ((s) == 1) a1 = (val);                   \
    else if ((s) == 2) a2 = (val);                   \
    else               a3 = (val); } while (0)

__global__ __launch_bounds__(32, 1)
void lsap_warp_kernel(const float* __restrict__ D, float* __restrict__ out) {
    extern __shared__ float Cs[];              // NN*NN floats (64KB)
    __shared__ float u_s[NN], du_s[NN];
    __shared__ int   claim_s[NN], c4r_s[NN];
    __shared__ int   list_s[LIST_CAP];

    const int lane = threadIdx.x;
    const int b    = blockIdx.x;
    const int base = lane << 2;
    const unsigned jid0 = base, jid1 = base + 1, jid2 = base + 2, jid3 = base + 3;

    // ---- load cost matrix (coalesced float4) ----
    {
        const float4* src = reinterpret_cast<const float4*>(D + (size_t)b * NN * NN);
        float4* dst = reinterpret_cast<float4*>(Cs);
        #pragma unroll 8
        for (int k = lane; k < NN * NN / 4; k += 32) dst[k] = src[k];
    }
    *reinterpret_cast<float4*>(u_s + base) = make_float4(0.f, 0.f, 0.f, 0.f);
    *reinterpret_cast<int4*>(claim_s + base) =
        make_int4(0x7FFFFFFF, 0x7FFFFFFF, 0x7FFFFFFF, 0x7FFFFFFF);
    *reinterpret_cast<int4*>(c4r_s + base) = make_int4(-1, -1, -1, -1);
    __syncwarp();

    // ================= Phase A: column reduction =================
    float cm0 = INF_F, cm1 = INF_F, cm2 = INF_F, cm3 = INF_F;
    int   am0 = 0, am1 = 0, am2 = 0, am3 = 0;
    #pragma unroll 4
    for (int i = 0; i < NN; ++i) {
        const float4 cr = *reinterpret_cast<const float4*>(Cs + i * NN + base);
        if (cr.x < cm0) { cm0 = cr.x; am0 = i; }
        if (cr.y < cm1) { cm1 = cr.y; am1 = i; }
        if (cr.z < cm2) { cm2 = cr.z; am2 = i; }
        if (cr.w < cm3) { cm3 = cr.w; am3 = i; }
    }
    float v0 = cm0, v1 = cm1, v2 = cm2, v3 = cm3;

    atomicMin(&claim_s[am0], base);
    atomicMin(&claim_s[am1], base + 1);
    atomicMin(&claim_s[am2], base + 2);
    atomicMin(&claim_s[am3], base + 3);
    __syncwarp();
    int r4c0 = -1, r4c1 = -1, r4c2 = -1, r4c3 = -1;   // row4col (by column)
    if (claim_s[am0] == base)     { r4c0 = am0; c4r_s[am0] = base; }
    if (claim_s[am1] == base + 1) { r4c1 = am1; c4r_s[am1] = base + 1; }
    if (claim_s[am2] == base + 2) { r4c2 = am2; c4r_s[am2] = base + 2; }
    if (claim_s[am3] == base + 3) { r4c3 = am3; c4r_s[am3] = base + 3; }
    __syncwarp();
    const int4 ct = *reinterpret_cast<const int4*>(c4r_s + base);
    int c4r0 = ct.x, c4r1 = ct.y, c4r2 = ct.z, c4r3 = ct.w;  // col4row (by row)
    __syncwarp();

    // ============ Phase A': reduction transfer (assigned rows) =============
    for (int i = 0; i < NN; ++i) {
        const int mycI = SEL4(i & 3, c4r0, c4r1, c4r2, c4r3);
        const int j1 = __shfl_sync(FULL, mycI, i >> 2);
        if (j1 < 0) continue;                         // unassigned row

        const float4 cr = *reinterpret_cast<const float4*>(Cs + i * NN + base);
        float t0 = cr.x - v0, t1 = cr.y - v1;
        float t2 = cr.z - v2, t3 = cr.w - v3;
        const int l1 = j1 >> 2, s1 = j1 & 3;
        if (lane == l1) SET4(s1, t0, t1, t2, t3, INF_F);   // exclude j1
        const float bv = fminf(fminf(t0, t1), fminf(t2, t3));
        const float mu = __uint_as_float(
            __reduce_min_sync(FULL, __float_as_uint(bv)));  // exact (t>=0)
        if (lane == 0) u_s[i] = mu;
        if (lane == l1) {                              // v[j1] = C[i][j1] - mu
            const float cij = SEL4(s1, cr.x, cr.y, cr.z, cr.w);
            SET4(s1, v0, v1, v2, v3, cij - mu);
        }
    }
    __syncwarp();

    // ---- build free-row FIFO (deterministic ballot-scan order) ----
    int tail = 0;
    #pragma unroll
    for (int s = 0; s < 4; ++s) {
        const int flag = (SEL4(s, c4r0, c4r1, c4r2, c4r3) < 0);
        const unsigned bal = __ballot_sync(FULL, flag);
        if (flag)
            list_s[tail + __popc(bal & ((1u << lane) - 1u))] = base + s;
        tail += __popc(bal);
    }
    __syncwarp();

    // ============ Phase B: augmenting row reduction (FIFO, budgeted) =======
    {
        int head = 0, budget = ARR_BUDGET;
        while (head < tail && budget-- > 0) {
            const int i = list_s[head++];             // warp-uniform broadcast
            const int mycI = SEL4(i & 3, c4r0, c4r1, c4r2, c4r3);
            if (__shfl_sync(FULL, mycI, i >> 2) >= 0) continue;  // stale entry

            const float4 cr = *reinterpret_cast<const float4*>(Cs + i * NN + base);
            const float t0 = cr.x - v0, t1 = cr.y - v1;
            const float t2 = cr.z - v2, t3 = cr.w - v3;
            unsigned k0 = (__float_as_uint(t0) & 0xFFFFFF80u) | jid0;
            unsigned k1 = (__float_as_uint(t1) & 0xFFFFFF80u) | jid1;
            unsigned k2 = (__float_as_uint(t2) & 0xFFFFFF80u) | jid2;
            unsigned k3 = (__float_as_uint(t3) & 0xFFFFFF80u) | jid3;
            unsigned key = min(min(k0, k1), min(k2, k3));
            key = __reduce_min_sync(FULL, key);
            const int j1 = (int)(key & 127u), s1 = j1 & 3, l1 = j1 >> 2;
            const float candt = SEL4(s1, t0, t1, t2, t3);
            const float min1  = __shfl_sync(FULL, candt, l1);   // exact

            float e0 = t0, e1 = t1, e2 = t2, e3 = t3;
            if (lane == l1) SET4(s1, e0, e1, e2, e3, INF_F);
            const float bv2  = fminf(fminf(e0, e1), fminf(e2, e3));
            const float min2 = __uint_as_float(
                __reduce_min_sync(FULL, __float_as_uint(bv2)));  // exact (t>=0)

            const int candr = SEL4(s1, r4c0, r4c1, r4c2, r4c3);
            const int kprev = __shfl_sync(FULL, candr, l1);
            if (lane == 0) u_s[i] = min2;
            if (lane == l1) {
                SET4(s1, r4c0, r4c1, r4c2, r4c3, i);
                if (min1 < min2) {
                    const float nv = SEL4(s1, v0, v1, v2, v3) - (min2 - min1);
                    SET4(s1, v0, v1, v2, v3, nv);
                }
            }
            if (lane == (i >> 2)) SET4(i & 3, c4r0, c4r1, c4r2, c4r3, j1);
            if (kprev >= 0) {
                if (lane == (kprev >> 2))
                    SET4(kprev & 3, c4r0, c4r1, c4r2, c4r3, -1);
                if (lane == 0) list_s[tail] = kprev;   // re-enqueue displaced
                ++tail;
                __syncwarp();                           // publish list append
            }
        }
    }
    __syncwarp();

    // ---- rebuild surviving free-row list for Phase C ----
    tail = 0;
    #pragma unroll
    for (int s = 0; s < 4; ++s) {
        const int flag = (SEL4(s, c4r0, c4r1, c4r2, c4r3) < 0);
        const unsigned bal = __ballot_sync(FULL, flag);
        if (flag)
            list_s[tail + __popc(bal & ((1u << lane) - 1u))] = base + s;
        tail += __popc(bal);
    }
    __syncwarp();

    // ================= Phase C: shortest augmenting path ====================
    for (int t = 0; t < tail; ++t) {
        const int cur = list_s[t];                   // free row (warp-uniform)

        // phase-constant packed row4col (+1, 8 bits); injective on assigned
        const unsigned q0 = (unsigned)(r4c0 + 1), q1 = (unsigned)(r4c1 + 1);
        const unsigned q2 = (unsigned)(r4c2 + 1), q3 = (unsigned)(r4c3 + 1);
        unsigned k0 = 0xFFFFFFFFu, k1 = 0xFFFFFFFFu,
                 k2 = 0xFFFFFFFFu, k3 = 0xFFFFFFFFu;   // biased sp keys
        int   p0 = 0, p1 = 0, p2 = 0, p3 = 0;           // predecessors
        float w0 = v0, w1 = v1, w2 = v2, w3 = v3;       // working duals
        float fz0 = 0, fz1 = 0, fz2 = 0, fz3 = 0;       // frozen values (regs)
        {   // du init with BIAS seeded at cur's owner slot
            float4 di = make_float4(DU_SENT, DU_SENT, DU_SENT, DU_SENT);
            if (lane == (cur >> 2)) {
                if      ((cur & 3) == 0) di.x = BIAS;
                else if ((cur & 3) == 1) di.y = BIAS;
                else if ((cur & 3) == 2) di.z = BIAS;
                else                     di.w = BIAS;
            }
            *reinterpret_cast<float4*>(du_s + base) = di;
        }

        float mb = BIAS;                                 // biased potential
        int   i  = cur;
        int   sink;
        unsigned wb;                                     // winning key

        while (true) {
            const float c = mb - u_s[i];
            const float4 cr = *reinterpret_cast<const float4*>(Cs + i * NN + base);
            // frozen: w=-1e30 -> rm == exactly 1e30 -> key == FROZEN_KEY|q >= k
            const float rm0 = cr.x + (c - w0);
            const float rm1 = cr.y + (c - w1);
            const float rm2 = cr.z + (c - w2);
            const float rm3 = cr.w + (c - w3);
            // rm biased positive => raw bits are order-correct
            const unsigned n0 = (__float_as_uint(rm0) & VMASK) | q0;
            const unsigned n1 = (__float_as_uint(rm1) & VMASK) | q1;
            const unsigned n2 = (__float_as_uint(rm2) & VMASK) | q2;
            const unsigned n3 = (__float_as_uint(rm3) & VMASK) | q3;
            if (n0 < k0) { k0 = n0; p0 = i; }
            if (n1 < k1) { k1 = n1; p1 = i; }
            if (n2 < k2) { k2 = n2; p2 = i; }
            if (n3 < k3) { k3 = n3; p3 = i; }

            wb = __reduce_min_sync(FULL, min(min(k0, k1), min(k2, k3)));
            mb = __uint_as_float(wb & VMASK);            // popped biased value
            const int r4f = (int)(wb & 0xFFu);           // row4col[j] + 1
            if (r4f == 0) break;                         // sink: elect j below
            // freeze winning column (unique key: r4 injective when r4f>0)
            if (wb == k0) { k0 = FROZEN_KEY; w0 = NEG_BIG; fz0 = mb; }
            else if (wb == k1) { k1 = FROZEN_KEY; w1 = NEG_BIG; fz1 = mb; }
            else if (wb == k2) { k2 = FROZEN_KEY; w2 = NEG_BIG; fz2 = mb; }
            else if (wb == k3) { k3 = FROZEN_KEY; w3 = NEG_BIG; fz3 = mb; }
            const int r4 = r4f - 1;
            if (lane == 0) du_s[r4] = mb;                // row r4 enters SR
            i = r4;
        }

        // elect sink column among (possibly tied) unassigned winners
        {
            int m = (k0 == wb) ? 1 : ((k1 == wb) ? 2 : ((k2 == wb) ? 3 : ((k3 == wb) ? 4 : 0)));
            const unsigned bal = __ballot_sync(FULL, m != 0);
            const int leader = __ffs((int)bal) - 1;
            const int jc = base + m - 1;
            sink = __shfl_sync(FULL, jc, leader);
        }

        __syncwarp();     // lane0's du_s stores -> owner-lane reads
        // dual updates: biases cancel exactly in (mbf - du) and (mbf - fz)
        const float mbf = mb;
        {
            const float4 du = *reinterpret_cast<const float4*>(du_s + base);
            float4 uu = *reinterpret_cast<float4*>(u_s + base);
            if (du.x > -1e29f) uu.x += mbf - du.x;
            if (du.y > -1e29f) uu.y += mbf - du.y;
            if (du.z > -1e29f) uu.z += mbf - du.z;
            if (du.w > -1e29f) uu.w += mbf - du.w;
            *reinterpret_cast<float4*>(u_s + base) = uu;
        }
        if (w0 == NEG_BIG) v0 -= mbf - fz0;
        if (w1 == NEG_BIG) v1 -= mbf - fz1;
        if (w2 == NEG_BIG) v2 -= mbf - fz2;
        if (w3 == NEG_BIG) v3 -= mbf - fz3;

        // augment alternating path (cooperative shfl walk)
        int j = sink;
        while (true) {
            const int sj = j & 3, lj = j >> 2;
            const int myp = SEL4(sj, p0, p1, p2, p3);
            const int ii  = __shfl_sync(FULL, myp, lj);      // i = path[j]
            if (lane == lj) SET4(sj, r4c0, r4c1, r4c2, r4c3, ii);
            const int si = ii & 3, li = ii >> 2;
            const int myc = SEL4(si, c4r0, c4r1, c4r2, c4r3);
            const int jn  = __shfl_sync(FULL, myc, li);      // jn = col4row[i]
            if (lane == li) SET4(si, c4r0, c4r1, c4r2, c4r3, j);
            j = jn;
            if (ii == cur) break;
        }
        __syncwarp();     // u_s updates visible before next phase reads
    }

    // ---- sum matched original entries, then cross-CTA completion ----
    float m = Cs[(base)     * NN + c4r0]
            + Cs[(base + 1) * NN + c4r1]
            + Cs[(base + 2) * NN + c4r2]
            + Cs[(base + 3) * NN + c4r3];
    #pragma unroll
    for (int off = 16; off > 0; off >>= 1)
        m += __shfl_down_sync(FULL, m, off);

    int last = 0;
    if (lane == 0) {
        g_partial[b] = m;
        __threadfence();
        last = (atomicAdd(&g_count, 1u) == BATCH - 1);
    }
    if (__shfl_sync(FULL, last, 0)) {
        __threadfence();
        volatile float* gp = g_partial;
        float s = gp[base] + gp[base + 1] + gp[base + 2] + gp[base + 3];
        #pragma unroll
        for (int off = 16; off > 0; off >>= 1)
            s += __shfl_down_sync(FULL, s, off);
        if (lane == 0) {
            out[0] = s * (1.0f / (float)(NN * BATCH));
            g_count = 0;                       // reset for next graph replay
        }
    }
}

extern "C" void kernel_launch(void* const* d_in, const int* in_sizes, int n_in,
                              void* d_out, int out_size) {
    (void)in_sizes; (void)n_in; (void)out_size;
    const float* D = (const float*)d_in[0];
    float* out = (float*)d_out;

    const int smem = NN * NN * (int)sizeof(float);   // 64KB dynamic
    cudaFuncSetAttribute(lsap_warp_kernel,
                         cudaFuncAttributeMaxDynamicSharedMemorySize, smem);

    lsap_warp_kernel<<<BATCH, 32, smem>>>(D, out);
}

// round 17
// speedup vs baseline: 2.2473x; 2.2473x over previous
#include <cuda_runtime.h>
#include <cuda_bf16.h>

// Batched LSAP -> mean of matched original entries, one warp per matrix.
// Normalization skipped (monotone affine => same optimal assignment).
//
// Classical Jonker-Volgenant per matrix (lane L owns cols/rows {4L..4L+3}):
//   A)  column reduction (v[j]=min_i C[i,j], argmin rows claimed)
//   A') reduction transfer: for assigned row i matched to j1,
//       mu = min_{j!=j1}(C[i,j]-v[j]); u[i]=mu; v[j1]=C[i,j1]-mu.
//   B)  EXACTLY TWO augmenting-row-reduction sweeps (convergence ARR thrashes:
//       displacement cycles burn cycles without reducing SAP work -- measured).
//       Each sweep iterates a ballot-scan free-row list; list entries are
//       provably still free at their turn (only processed rows get assigned,
//       only non-list rows get displaced), so no staleness checks.
//   C)  shortest augmenting path over the surviving free list, with BIASED
//       (+4) positive potentials: raw float bits are order-correct, so
//         key = (bits(rm) & 0xFFFFFF00) | (row4col[col]+1)
//       and one __reduce_min_sync yields next row AND popped potential.
//       Frozen columns: w=-1e30 -> rm == exactly 1e30 -> self-excluding keys.

#define NN 128
#define BATCH 128
#define INF_F   1e30f
#define NEG_BIG -1e30f
#define DU_SENT -1e30f
#define BIAS    4.0f
#define FULL 0xffffffffu
#define VMASK 0xFFFFFF00u
#define FROZEN_KEY 0x7149F200u   /* __float_as_uint(1e30f) & VMASK */

__device__ float g_partial[BATCH];
__device__ unsigned g_count = 0;

#define SEL4(s, a0, a1, a2, a3) ((s) < 2 ? ((s) == 0 ? (a0) : (a1)) \
                                         : ((s) == 2 ? (a2) : (a3)))
#define SET4(s, a0, a1, a2, a3, val) do {            \
    if      ((s) == 0) a0 = (val);                   \
    else if ((s) == 1) a1 = (val);                   \
    else if ((s) == 2) a2 = (val);                   \
    else               a3 = (val); } while (0)

// build free-row list from col4row registers via ballot scan; returns count
#define BUILD_FREE_LIST(tail) do {                                        \
    (tail) = 0;                                                           \
    _Pragma("unroll")                                                     \
    for (int s_ = 0; s_ < 4; ++s_) {                                      \
        const int flag_ = (SEL4(s_, c4r0, c4r1, c4r2, c4r3) < 0);         \
        const unsigned bal_ = __ballot_sync(FULL, flag_);                 \
        if (flag_)                                                        \
            list_s[(tail) + __popc(bal_ & ((1u << lane) - 1u))] = base + s_; \
        (tail) += __popc(bal_);                                           \
    }                                                                     \
    __syncwarp();                                                         \
} while (0)

__global__ __launch_bounds__(32, 1)
void lsap_warp_kernel(const float* __restrict__ D, float* __restrict__ out) {
    extern __shared__ float Cs[];              // NN*NN floats (64KB)
    __shared__ float u_s[NN], du_s[NN];
    __shared__ int   claim_s[NN], list_s[NN];

    const int lane = threadIdx.x;
    const int b    = blockIdx.x;
    const int base = lane << 2;
    const unsigned jid0 = base, jid1 = base + 1, jid2 = base + 2, jid3 = base + 3;

    // ---- load cost matrix (coalesced float4) ----
    {
        const float4* src = reinterpret_cast<const float4*>(D + (size_t)b * NN * NN);
        float4* dst = reinterpret_cast<float4*>(Cs);
        #pragma unroll 8
        for (int k = lane; k < NN * NN / 4; k += 32) dst[k] = src[k];
    }
    *reinterpret_cast<float4*>(u_s + base) = make_float4(0.f, 0.f, 0.f, 0.f);
    *reinterpret_cast<int4*>(claim_s + base) =
        make_int4(0x7FFFFFFF, 0x7FFFFFFF, 0x7FFFFFFF, 0x7FFFFFFF);
    __syncwarp();

    // ================= Phase A: column reduction =================
    float cm0 = INF_F, cm1 = INF_F, cm2 = INF_F, cm3 = INF_F;
    int   am0 = 0, am1 = 0, am2 = 0, am3 = 0;
    #pragma unroll 4
    for (int i = 0; i < NN; ++i) {
        const float4 cr = *reinterpret_cast<const float4*>(Cs + i * NN + base);
        if (cr.x < cm0) { cm0 = cr.x; am0 = i; }
        if (cr.y < cm1) { cm1 = cr.y; am1 = i; }
        if (cr.z < cm2) { cm2 = cr.z; am2 = i; }
        if (cr.w < cm3) { cm3 = cr.w; am3 = i; }
    }
    float v0 = cm0, v1 = cm1, v2 = cm2, v3 = cm3;

    atomicMin(&claim_s[am0], base);
    atomicMin(&claim_s[am1], base + 1);
    atomicMin(&claim_s[am2], base + 2);
    atomicMin(&claim_s[am3], base + 3);
    __syncwarp();
    int r4c0 = -1, r4c1 = -1, r4c2 = -1, r4c3 = -1;   // row4col (by column)
    // reuse du_s as temporary c4r broadcast buffer
    int* c4rtmp = (int*)du_s;
    *reinterpret_cast<int4*>(c4rtmp + base) = make_int4(-1, -1, -1, -1);
    __syncwarp();
    if (claim_s[am0] == base)     { r4c0 = am0; c4rtmp[am0] = base; }
    if (claim_s[am1] == base + 1) { r4c1 = am1; c4rtmp[am1] = base + 1; }
    if (claim_s[am2] == base + 2) { r4c2 = am2; c4rtmp[am2] = base + 2; }
    if (claim_s[am3] == base + 3) { r4c3 = am3; c4rtmp[am3] = base + 3; }
    __syncwarp();
    const int4 ct = *reinterpret_cast<const int4*>(c4rtmp + base);
    int c4r0 = ct.x, c4r1 = ct.y, c4r2 = ct.z, c4r3 = ct.w;  // col4row (by row)
    __syncwarp();

    // ============ Phase A': reduction transfer (assigned rows) =============
    for (int i = 0; i < NN; ++i) {
        const int mycI = SEL4(i & 3, c4r0, c4r1, c4r2, c4r3);
        const int j1 = __shfl_sync(FULL, mycI, i >> 2);
        if (j1 < 0) continue;                         // unassigned row

        const float4 cr = *reinterpret_cast<const float4*>(Cs + i * NN + base);
        float t0 = cr.x - v0, t1 = cr.y - v1;
        float t2 = cr.z - v2, t3 = cr.w - v3;
        const int l1 = j1 >> 2, s1 = j1 & 3;
        if (lane == l1) SET4(s1, t0, t1, t2, t3, INF_F);   // exclude j1
        const float bv = fminf(fminf(t0, t1), fminf(t2, t3));
        const float mu = __uint_as_float(
            __reduce_min_sync(FULL, __float_as_uint(bv)));  // exact (t>=0)
        if (lane == 0) u_s[i] = mu;
        if (lane == l1) {                              // v[j1] = C[i][j1] - mu
            const float cij = SEL4(s1, cr.x, cr.y, cr.z, cr.w);
            SET4(s1, v0, v1, v2, v3, cij - mu);
        }
    }
    __syncwarp();

    // ========== Phase B: exactly two ARR sweeps over free lists ============
    int tail;
    for (int pass = 0; pass < 2; ++pass) {
        BUILD_FREE_LIST(tail);
        for (int t = 0; t < tail; ++t) {
            const int i = list_s[t];                  // provably still free

            const float4 cr = *reinterpret_cast<const float4*>(Cs + i * NN + base);
            const float t0 = cr.x - v0, t1 = cr.y - v1;
            const float t2 = cr.z - v2, t3 = cr.w - v3;
            unsigned k0 = (__float_as_uint(t0) & 0xFFFFFF80u) | jid0;
            unsigned k1 = (__float_as_uint(t1) & 0xFFFFFF80u) | jid1;
            unsigned k2 = (__float_as_uint(t2) & 0xFFFFFF80u) | jid2;
            unsigned k3 = (__float_as_uint(t3) & 0xFFFFFF80u) | jid3;
            unsigned key = min(min(k0, k1), min(k2, k3));
            key = __reduce_min_sync(FULL, key);
            const int j1 = (int)(key & 127u), s1 = j1 & 3, l1 = j1 >> 2;
            const float candt = SEL4(s1, t0, t1, t2, t3);
            const float min1  = __shfl_sync(FULL, candt, l1);   // exact

            float e0 = t0, e1 = t1, e2 = t2, e3 = t3;
            if (lane == l1) SET4(s1, e0, e1, e2, e3, INF_F);
            const float bv2  = fminf(fminf(e0, e1), fminf(e2, e3));
            const float min2 = __uint_as_float(
                __reduce_min_sync(FULL, __float_as_uint(bv2)));  // exact (t>=0)

            const int candr = SEL4(s1, r4c0, r4c1, r4c2, r4c3);
            const int kprev = __shfl_sync(FULL, candr, l1);
            if (lane == 0) u_s[i] = min2;
            if (lane == l1) {
                SET4(s1, r4c0, r4c1, r4c2, r4c3, i);
                if (min1 < min2) {
                    const float nv = SEL4(s1, v0, v1, v2, v3) - (min2 - min1);
                    SET4(s1, v0, v1, v2, v3, nv);
                }
            }
            if (lane == (i >> 2)) SET4(i & 3, c4r0, c4r1, c4r2, c4r3, j1);
            if (kprev >= 0 && lane == (kprev >> 2))
                SET4(kprev & 3, c4r0, c4r1, c4r2, c4r3, -1);
        }
    }
    __syncwarp();

    // ---- free-row list for Phase C ----
    BUILD_FREE_LIST(tail);

    // ================= Phase C: shortest augmenting path ====================
    for (int t = 0; t < tail; ++t) {
        const int cur = list_s[t];                   // still free at its turn

        // phase-constant packed row4col (+1, 8 bits); injective on assigned
        const unsigned q0 = (unsigned)(r4c0 + 1), q1 = (unsigned)(r4c1 + 1);
        const unsigned q2 = (unsigned)(r4c2 + 1), q3 = (unsigned)(r4c3 + 1);
        unsigned k0 = 0xFFFFFFFFu, k1 = 0xFFFFFFFFu,
                 k2 = 0xFFFFFFFFu, k3 = 0xFFFFFFFFu;   // biased sp keys
        int   p0 = 0, p1 = 0, p2 = 0, p3 = 0;           // predecessors
        float w0 = v0, w1 = v1, w2 = v2, w3 = v3;       // working duals
        float fz0 = 0, fz1 = 0, fz2 = 0, fz3 = 0;       // frozen values (regs)
        {   // du init with BIAS seeded at cur's owner slot
            float4 di = make_float4(DU_SENT, DU_SENT, DU_SENT, DU_SENT);
            if (lane == (cur >> 2)) {
                if      ((cur & 3) == 0) di.x = BIAS;
                else if ((cur & 3) == 1) di.y = BIAS;
                else if ((cur & 3) == 2) di.z = BIAS;
                else                     di.w = BIAS;
            }
            *reinterpret_cast<float4*>(du_s + base) = di;
        }

        float mb = BIAS;                                 // biased potential
        int   i  = cur;
        int   sink;
        unsigned wb;                                     // winning key

        while (true) {
            const float c = mb - u_s[i];
            const float4 cr = *reinterpret_cast<const float4*>(Cs + i * NN + base);
            // frozen: w=-1e30 -> rm == exactly 1e30 -> key == FROZEN_KEY|q >= k
            const float rm0 = cr.x + (c - w0);
            const float rm1 = cr.y + (c - w1);
            const float rm2 = cr.z + (c - w2);
            const float rm3 = cr.w + (c - w3);
            // rm biased positive => raw bits are order-correct
            const unsigned n0 = (__float_as_uint(rm0) & VMASK) | q0;
            const unsigned n1 = (__float_as_uint(rm1) & VMASK) | q1;
            const unsigned n2 = (__float_as_uint(rm2) & VMASK) | q2;
            const unsigned n3 = (__float_as_uint(rm3) & VMASK) | q3;
            if (n0 < k0) { k0 = n0; p0 = i; }
            if (n1 < k1) { k1 = n1; p1 = i; }
            if (n2 < k2) { k2 = n2; p2 = i; }
            if (n3 < k3) { k3 = n3; p3 = i; }

            wb = __reduce_min_sync(FULL, min(min(k0, k1), min(k2, k3)));
            mb = __uint_as_float(wb & VMASK);            // popped biased value
            const int r4f = (int)(wb & 0xFFu);           // row4col[j] + 1
            if (r4f == 0) break;                         // sink: elect j below
            // freeze winning column (unique key: r4 injective when r4f>0)
            if (wb == k0) { k0 = FROZEN_KEY; w0 = NEG_BIG; fz0 = mb; }
            else if (wb == k1) { k1 = FROZEN_KEY; w1 = NEG_BIG; fz1 = mb; }
            else if (wb == k2) { k2 = FROZEN_KEY; w2 = NEG_BIG; fz2 = mb; }
            else if (wb == k3) { k3 = FROZEN_KEY; w3 = NEG_BIG; fz3 = mb; }
            const int r4 = r4f - 1;
            if (lane == 0) du_s[r4] = mb;                // row r4 enters SR
            i = r4;
        }

        // elect sink column among (possibly tied) unassigned winners
        {
            int m = (k0 == wb) ? 1 : ((k1 == wb) ? 2 : ((k2 == wb) ? 3 : ((k3 == wb) ? 4 : 0)));
            const unsigned bal = __ballot_sync(FULL, m != 0);
            const int leader = __ffs((int)bal) - 1;
            const int jc = base + m - 1;
            sink = __shfl_sync(FULL, jc, leader);
        }

        __syncwarp();     // lane0's du_s stores -> owner-lane reads
        // dual updates: biases cancel exactly in (mbf - du) and (mbf - fz)
        const float mbf = mb;
        {
            const float4 du = *reinterpret_cast<const float4*>(du_s + base);
            float4 uu = *reinterpret_cast<float4*>(u_s + base);
            if (du.x > -1e29f) uu.x += mbf - du.x;
            if (du.y > -1e29f) uu.y += mbf - du.y;
            if (du.z > -1e29f) uu.z += mbf - du.z;
            if (du.w > -1e29f) uu.w += mbf - du.w;
            *reinterpret_cast<float4*>(u_s + base) = uu;
        }
        if (w0 == NEG_BIG) v0 -= mbf - fz0;
        if (w1 == NEG_BIG) v1 -= mbf - fz1;
        if (w2 == NEG_BIG) v2 -= mbf - fz2;
        if (w3 == NEG_BIG) v3 -= mbf - fz3;

        // augment alternating path (cooperative shfl walk)
        int j = sink;
        while (true) {
            const int sj = j & 3, lj = j >> 2;
            const int myp = SEL4(sj, p0, p1, p2, p3);
            const int ii  = __shfl_sync(FULL, myp, lj);      // i = path[j]
            if (lane == lj) SET4(sj, r4c0, r4c1, r4c2, r4c3, ii);
            const int si = ii & 3, li = ii >> 2;
            const int myc = SEL4(si, c4r0, c4r1, c4r2, c4r3);
            const int jn  = __shfl_sync(FULL, myc, li);      // jn = col4row[i]
            if (lane == li) SET4(si, c4r0, c4r1, c4r2, c4r3, j);
            j = jn;
            if (ii == cur) break;
        }
        __syncwarp();     // u_s updates visible before next phase reads
    }

    // ---- sum matched original entries, then cross-CTA completion ----
    float m = Cs[(base)     * NN + c4r0]
            + Cs[(base + 1) * NN + c4r1]
            + Cs[(base + 2) * NN + c4r2]
            + Cs[(base + 3) * NN + c4r3];
    #pragma unroll
    for (int off = 16; off > 0; off >>= 1)
        m += __shfl_down_sync(FULL, m, off);

    int last = 0;
    if (lane == 0) {
        g_partial[b] = m;
        __threadfence();
        last = (atomicAdd(&g_count, 1u) == BATCH - 1);
    }
    if (__shfl_sync(FULL, last, 0)) {
        __threadfence();
        volatile float* gp = g_partial;
        float s = gp[base] + gp[base + 1] + gp[base + 2] + gp[base + 3];
        #pragma unroll
        for (int off = 16; off > 0; off >>= 1)
            s += __shfl_down_sync(FULL, s, off);
        if (lane == 0) {
            out[0] = s * (1.0f / (float)(NN * BATCH));
            g_count = 0;                       // reset for next graph replay
        }
    }
}

extern "C" void kernel_launch(void* const* d_in, const int* in_sizes, int n_in,
                              void* d_out, int out_size) {
    (void)in_sizes; (void)n_in; (void)out_size;
    const float* D = (const float*)d_in[0];
    float* out = (float*)d_out;

    const int smem = NN * NN * (int)sizeof(float);   // 64KB dynamic
    cudaFuncSetAttribute(lsap_warp_kernel,
                         cudaFuncAttributeMaxDynamicSharedMemorySize, smem);

    lsap_warp_kernel<<<BATCH, 32, smem>>>(D, out);
}